// round 15
// baseline (speedup 1.0000x reference)
#include <cuda_runtime.h>
#include <cuda_fp16.h>
#include <math.h>

#define Hh 240
#define Ww 240
#define NPIX 57600           // 240*240
#define BMAX 256
#define RSTRIDE 241          // smem row stride in float2 (241 ≡ 1 mod 16 -> conflict-free)

// ---------------- scratch (no cudaMalloc allowed) ----------------
// g_s1h holds only the Hermitian-unique half: kw in [0,128)
__device__ __half2 g_s1h[BMAX * 128 * 240];  // after K1: [b][kw<128][h] (re,im) fp16
__device__ __half2 g_s2h[BMAX * NPIX];       // after K2: [b][h][kw]     (re,im) fp16
__device__ float2 g_tw[240];                 // forward twiddles e^{-2*pi*i*j/240}

// ---------------- complex helpers ----------------
__device__ __forceinline__ float2 cadd(float2 a, float2 b){ return make_float2(a.x+b.x, a.y+b.y); }
__device__ __forceinline__ float2 csub(float2 a, float2 b){ return make_float2(a.x-b.x, a.y-b.y); }
__device__ __forceinline__ float2 cmul(float2 a, float2 b){
    return make_float2(a.x*b.x - a.y*b.y, a.x*b.y + a.y*b.x);
}

// DIR = -1 forward (e^{-i}), +1 inverse (e^{+i})
template<int DIR>
__device__ __forceinline__ void dft4(float2 a[4]) {
    float2 u0 = cadd(a[0], a[2]);
    float2 u1 = csub(a[0], a[2]);
    float2 u2 = cadd(a[1], a[3]);
    float2 u3 = csub(a[1], a[3]);
    float2 j3 = make_float2((DIR < 0) ? u3.y : -u3.y, (DIR < 0) ? -u3.x : u3.x);
    a[0] = cadd(u0, u2);
    a[2] = csub(u0, u2);
    a[1] = cadd(u1, j3);
    a[3] = csub(u1, j3);
}

__device__ __constant__ float C16c[10] = {1.f,0.92387953f,0.70710678f,0.38268343f,0.f,-0.38268343f,-0.70710678f,-0.92387953f,-1.f,-0.92387953f};
__device__ __constant__ float S16c[10] = {0.f,0.38268343f,0.70710678f,0.92387953f,1.f,0.92387953f,0.70710678f,0.38268343f,0.f,-0.38268343f};
__device__ __constant__ float C15c[9] = {1.f,0.91354546f,0.66913061f,0.30901699f,-0.10452846f,-0.5f,-0.80901699f,-0.97814760f,-0.97814760f};
__device__ __constant__ float S15c[9] = {0.f,0.40673664f,0.74314483f,0.95105652f,0.99452190f,0.86602540f,0.58778525f,0.20791169f,-0.20791169f};

template<int DIR>
__device__ __forceinline__ void fft16(float2 a[16]) {
    float2 b[4][4];
#pragma unroll
    for (int n2 = 0; n2 < 4; n2++) {
        float2 t[4];
#pragma unroll
        for (int n1 = 0; n1 < 4; n1++) t[n1] = a[4*n1 + n2];
        dft4<DIR>(t);
#pragma unroll
        for (int k1 = 0; k1 < 4; k1++) {
            const int j = n2 * k1;
            float2 w = make_float2(C16c[j], (DIR < 0) ? -S16c[j] : S16c[j]);
            b[n2][k1] = cmul(t[k1], w);
        }
    }
#pragma unroll
    for (int k1 = 0; k1 < 4; k1++) {
        float2 t[4];
#pragma unroll
        for (int n2 = 0; n2 < 4; n2++) t[n2] = b[n2][k1];
        dft4<DIR>(t);
#pragma unroll
        for (int k2 = 0; k2 < 4; k2++) a[k1 + 4*k2] = t[k2];
    }
}

template<int DIR>
__device__ __forceinline__ void dft5(float2 a[5]) {
    const float c1 = 0.309016994f, s1 = 0.951056516f;
    const float c2 = -0.809016994f, s2 = 0.587785252f;
    float2 a0 = a[0];
    float2 t1 = cadd(a[1], a[4]);
    float2 t2 = cadd(a[2], a[3]);
    float2 t3 = csub(a[1], a[4]);
    float2 t4 = csub(a[2], a[3]);
    float2 m1 = make_float2(a0.x + c1*t1.x + c2*t2.x, a0.y + c1*t1.y + c2*t2.y);
    float2 m2 = make_float2(a0.x + c2*t1.x + c1*t2.x, a0.y + c2*t1.y + c1*t2.y);
    float2 p1 = make_float2(s1*t3.x + s2*t4.x, s1*t3.y + s2*t4.y);
    float2 p2 = make_float2(s2*t3.x - s1*t4.x, s2*t3.y - s1*t4.y);
    float2 j1 = make_float2((DIR < 0) ? p1.y : -p1.y, (DIR < 0) ? -p1.x : p1.x);
    float2 j2 = make_float2((DIR < 0) ? p2.y : -p2.y, (DIR < 0) ? -p2.x : p2.x);
    a[0] = make_float2(a0.x + t1.x + t2.x, a0.y + t1.y + t2.y);
    a[1] = cadd(m1, j1);
    a[4] = csub(m1, j1);
    a[2] = cadd(m2, j2);
    a[3] = csub(m2, j2);
}

template<int DIR>
__device__ __forceinline__ void dft3(float2 a[3]) {
    const float s3 = 0.866025404f;
    float2 a0 = a[0];
    float2 t1 = cadd(a[1], a[2]);
    float2 t2 = csub(a[1], a[2]);
    float2 m = make_float2(a0.x - 0.5f*t1.x, a0.y - 0.5f*t1.y);
    float2 jt = make_float2((DIR < 0) ? s3*t2.y : -s3*t2.y, (DIR < 0) ? -s3*t2.x : s3*t2.x);
    a[0] = make_float2(a0.x + t1.x, a0.y + t1.y);
    a[1] = cadd(m, jt);
    a[2] = csub(m, jt);
}

template<int DIR>
__device__ __forceinline__ void fft15(float2 a[15]) {
    float2 c[3][5];
#pragma unroll
    for (int m2 = 0; m2 < 3; m2++) {
        float2 t[5];
#pragma unroll
        for (int m1 = 0; m1 < 5; m1++) t[m1] = a[3*m1 + m2];
        dft5<DIR>(t);
#pragma unroll
        for (int p1 = 0; p1 < 5; p1++) {
            const int j = m2 * p1;
            float2 w = make_float2(C15c[j], (DIR < 0) ? -S15c[j] : S15c[j]);
            c[m2][p1] = cmul(t[p1], w);
        }
    }
#pragma unroll
    for (int p1 = 0; p1 < 5; p1++) {
        float2 t[3] = {c[0][p1], c[1][p1], c[2][p1]};
        dft3<DIR>(t);
        a[p1]      = t[0];
        a[p1 + 5]  = t[1];
        a[p1 + 10] = t[2];
    }
}

// ---- stage pieces on an AOS float2 smem row v[240] (stride-241 rows) ----

template<int DIR>
__device__ __forceinline__ void stage1_tail(float2 a[16], float2* v, int t) {
#pragma unroll
    for (int k1 = 1; k1 < 16; k1++) {
        float2 w = __ldg(&g_tw[t * k1]);
        if (DIR > 0) w.y = -w.y;
        a[k1] = cmul(a[k1], w);
    }
#pragma unroll
    for (int k1 = 0; k1 < 16; k1++) v[15*k1 + t] = a[k1];
}

template<int DIR>
__device__ __forceinline__ void stage1_s(float2* v, int t) {
    if (t < 15) {
        float2 a[16];
#pragma unroll
        for (int n1 = 0; n1 < 16; n1++) a[n1] = v[15*n1 + t];
        fft16<DIR>(a);
        stage1_tail<DIR>(a, v, t);
    }
    __syncwarp();
}

// stage 1, complex fp16 inputs from global (L2-resident scratch, last use)
template<int DIR>
__device__ __forceinline__ void stage1_gh(const __half2* __restrict__ gsrc,
                                          float2* v, int t) {
    if (t < 15) {
        float2 a[16];
#pragma unroll
        for (int n1 = 0; n1 < 16; n1++) a[n1] = __half22float2(__ldcs(&gsrc[15*n1 + t]));
        fft16<DIR>(a);
        stage1_tail<DIR>(a, v, t);
    }
    __syncwarp();
}

// stage 1, PACKED pair of real rows (a + i*b) loaded directly from global
__device__ __forceinline__ void stage1_g_pair(const float* __restrict__ ra,
                                              const float* __restrict__ rb,
                                              float2* v, int t) {
    if (t < 15) {
        float2 a[16];
#pragma unroll
        for (int n1 = 0; n1 < 16; n1++)
            a[n1] = make_float2(__ldcs(&ra[15*n1 + t]), __ldcs(&rb[15*n1 + t]));
        fft16<-1>(a);
        stage1_tail<-1>(a, v, t);
    }
    __syncwarp();
}

template<int DIR>
__device__ __forceinline__ void stage2(float2* v, int t) {
    float2 b[15];
#pragma unroll
    for (int n2 = 0; n2 < 15; n2++) b[n2] = v[15*t + n2];
    fft15<DIR>(b);
    __syncwarp();   // all cross-lane reads done before scattered writes
    const float sc = (DIR > 0) ? (1.0f / 240.0f) : 1.0f;
#pragma unroll
    for (int j = 0; j < 15; j++) v[t + 16*j] = make_float2(b[j].x * sc, b[j].y * sc);
    __syncwarp();
}

// stage 2 inverse + magnitude, stored DIRECTLY to global (row-contiguous dst)
__device__ __forceinline__ void stage2_mag_g(const float2* v, int t,
                                             float* __restrict__ gdst) {
    float2 b[15];
#pragma unroll
    for (int n2 = 0; n2 < 15; n2++) b[n2] = v[15*t + n2];
    fft15<1>(b);
    const float sc = 1.0f / 240.0f;
#pragma unroll
    for (int j = 0; j < 15; j++)
        gdst[t + 16*j] = sc * sqrtf(b[j].x * b[j].x + b[j].y * b[j].y);
}

// ---------------- kernels ----------------
__global__ void init_tw_kernel() {
    int j = threadIdx.x;
    if (j < 240) {
        float s, c;
        sincosf(-6.283185307179586f * (float)j / 240.0f, &s, &c);
        g_tw[j] = make_float2(c, s);
    }
}

// K1: packed forward row FFTs of real input -> g_s1h[b][kw<128][h]
// 384 threads, 12 warps; warp w does packed FFTs p=2w (h=0) and p=2w+1 (h=1);
// packed FFT p covers real rows (h0+2p, h0+2p+1).  grid.x = 5 (48 rows/block).
__global__ __launch_bounds__(384) void k_rowfft(const float* __restrict__ x) {
    __shared__ float2 S1[24 * RSTRIDE];
    const int b = blockIdx.y;
    const int h0 = blockIdx.x * 48;
    const int tid = threadIdx.x;
    const int w = tid >> 5, lane = tid & 31;
    const int t = lane & 15, h = lane >> 4;
    const int p = 2 * w + h;                 // packed index 0..23

    const float* ra = x + ((size_t)b * 240 + h0 + 2 * p) * 240;
    float2* v = S1 + p * RSTRIDE;
    stage1_g_pair(ra, ra + 240, v, t);
    stage2<-1>(v, t);
    __syncthreads();

    // separation + transposed fp16 store: Z = FFT(a+ib) ->
    //   A[k] = (Z[k]+conj(Z[m]))/2,  B[k] = -i(Z[k]-conj(Z[m]))/2,  m=(240-k)%240
    {
        const int hh = tid % 48;
        const int kwb = tid / 48;            // 0..7
        const int pp = hh >> 1, e = hh & 1;
        const float2* Z = S1 + pp * RSTRIDE;
        __half2* dst = g_s1h + ((size_t)b * 128) * 240 + h0 + hh;
#pragma unroll
        for (int jj = 0; jj < 16; jj++) {
            int kw = kwb * 16 + jj;          // 0..127
            int m = (kw == 0) ? 0 : 240 - kw;
            float2 z1 = Z[kw];
            float2 z2 = Z[m];
            float2 vo;
            if (e == 0) vo = make_float2(0.5f * (z1.x + z2.x), 0.5f * (z1.y - z2.y));
            else        vo = make_float2(0.5f * (z1.y + z2.y), 0.5f * (z2.x - z1.x));
            dst[(size_t)kw * 240] = __floats2half2_rn(vo.x, vo.y);
        }
    }
}

// K2: fwd column FFT of 16 primary cols (warps 0-7, deduped) + Hermitian mirror
// reconstruction + combine + 32 column IFFTs (all 16 warps).  512 threads.
__global__ __launch_bounds__(512, 2) void k_colfft(const float* __restrict__ yk,
                                                   const float* __restrict__ Am) {
    extern __shared__ float2 S2[];           // 32 rows x RSTRIDE
    const int b = blockIdx.y;
    const int kw0 = blockIdx.x * 16;     // blockIdx.x in [0,8) -> primaries 0..127
    const int tid = threadIdx.x;
    const int w = tid >> 5, lane = tid & 31;
    const int t = lane & 15;
    const int h = lane >> 4;

    // ---- forward FFT of 16 primary columns: warps 0-7 own rows 2w, 2w+1;
    // warps 8-15 go straight to the barrier (no duplicated loads/FLOPs) ----
    if (w < 8) {
        const int row = 2 * w + h;
        float2* v = S2 + row * RSTRIDE;
        const __half2* gsrc = g_s1h + ((size_t)b * 128 + kw0 + row) * 240;
        stage1_gh<-1>(gsrc, v, t);           // L2 hits from K1's fresh stores
        stage2<-1>(v, t);
    }
    __syncthreads();

    const float* yr = yk + (size_t)b * (2 * NPIX);
    const float* yi = yr + NPIX;

    // ---- mirror build + combine: row 16+v <- (1-A')*conj(rev(row v)) + y' ----
    {
        const int v = tid & 15;
        const int khb = tid >> 4;            // 0..31
        const int kwm = (240 - (kw0 + v)) % 240;
        const float2* P = S2 + v * RSTRIDE;
        float2* M = S2 + (16 + v) * RSTRIDE;
#pragma unroll
        for (int j = 0; j < 8; j++) {
            int kh = khb + 32 * j;
            if (kh < 240) {
                int s = (kh == 0) ? 0 : 240 - kh;
                int idx = kh * 240 + kwm;
                float a = 1.0f - __ldg(&Am[idx]);
                float2 z = P[s];
                M[kh] = make_float2( z.x * a + __ldcs(&yr[idx]),
                                    -z.y * a + __ldcs(&yi[idx]));
            }
        }
    }
    __syncthreads();

    // ---- primary combine in place ----
    {
        const int v = tid & 15;
        const int khb = tid >> 4;
        float2* P = S2 + v * RSTRIDE;
#pragma unroll
        for (int j = 0; j < 8; j++) {
            int kh = khb + 32 * j;
            if (kh < 240) {
                int idx = kh * 240 + kw0 + v;
                float a = 1.0f - __ldg(&Am[idx]);
                float2 z = P[kh];
                P[kh] = make_float2(z.x * a + __ldcs(&yr[idx]),
                                    z.y * a + __ldcs(&yi[idx]));
            }
        }
    }
    __syncthreads();

    // ---- inverse FFT of all 32 rows: warp w owns rows 2w, 2w+1 ----
    {
        float2* v = S2 + (2 * w + h) * RSTRIDE;
        stage1_s<1>(v, t);
        stage2<1>(v, t);
    }
    __syncthreads();

    // ---- transposed fp16 store: primaries always; mirrors only if kwm >= 128
    // (masks the redundant overlap -> each g_s2h word written exactly once) ----
    {
        const int v = tid & 15;
        const int hb = tid >> 4;             // 0..31
        const float2* P = S2 + v * RSTRIDE;
        const float2* M = S2 + (16 + v) * RSTRIDE;
        const int kwm = (240 - (kw0 + v)) % 240;
        __half2* dstP = g_s2h + (size_t)b * NPIX + kw0 + v;
        __half2* dstM = g_s2h + (size_t)b * NPIX + kwm;
        const bool storeM = (kwm >= 128);
#pragma unroll
        for (int j = 0; j < 8; j++) {
            int hh = hb + 32 * j;
            if (hh < 240) {
                float2 zp = P[hh];
                dstP[(size_t)hh * 240] = __floats2half2_rn(zp.x, zp.y);
                if (storeM) {
                    float2 zm = M[hh];
                    dstM[(size_t)hh * 240] = __floats2half2_rn(zm.x, zm.y);
                }
            }
        }
    }
}

// K3: inverse row FFTs + abs -> out[b][h][w]  (zero staging, no block sync)
__global__ __launch_bounds__(256) void k_invrow(float* __restrict__ out) {
    __shared__ float2 S3[16 * RSTRIDE];
    const int b = blockIdx.y;
    const int h0 = blockIdx.x * 16;
    const int tid = threadIdx.x;
    const int w = tid >> 5, lane = tid & 31;
    const int t = lane & 15, h = lane >> 4;

    float2* v = S3 + (2 * w + h) * RSTRIDE;

    const __half2* gsrc = g_s2h + ((size_t)b * 240 + h0 + 2 * w + h) * 240;
    stage1_gh<1>(gsrc, v, t);                // L2-resident fp16, last use

    float* ob = out + ((size_t)b * 240 + h0 + 2 * w + h) * 240;
    stage2_mag_g(v, t, ob);
}

extern "C" void kernel_launch(void* const* d_in, const int* in_sizes, int n_in,
                              void* d_out, int out_size) {
    const float* T2_Gen    = (const float*)d_in[0];  // [B,1,240,240] f32
    const float* underT2_K = (const float*)d_in[1];  // [B,2,240,240] f32
    const float* A         = (const float*)d_in[2];  // [240,240] f32
    float* out = (float*)d_out;

    int B = in_sizes[0] / NPIX;   // 256

    const int k2_smem = 32 * RSTRIDE * (int)sizeof(float2);   // 61,696 B
    cudaFuncSetAttribute(k_colfft, cudaFuncAttributeMaxDynamicSharedMemorySize, k2_smem);

    init_tw_kernel<<<1, 256>>>();
    k_rowfft<<<dim3(5, B), 384>>>(T2_Gen);
    k_colfft<<<dim3(8, B), 512, k2_smem>>>(underT2_K, A);
    k_invrow<<<dim3(15, B), 256>>>(out);
}

// round 16
// speedup vs baseline: 1.0959x; 1.0959x over previous
#include <cuda_runtime.h>
#include <cuda_fp16.h>
#include <math.h>

#define Hh 240
#define Ww 240
#define NPIX 57600           // 240*240
#define BMAX 256
#define RSTRIDE 241          // smem row stride in c64 (241 odd -> conflict-free rows)

// ---------------- scratch (no cudaMalloc allowed) ----------------
__device__ __half2 g_s1h[BMAX * 128 * 240];  // after K1: [b][kw<128][h] (re,im) fp16
__device__ __half2 g_s2h[BMAX * NPIX];       // after K2: [b][h][kw]     (re,im) fp16
__device__ float2 g_tw[240];                 // forward twiddles e^{-2*pi*i*j/240}

// ---------------- packed complex: (re,im) in one 64-bit register pair ----------------
typedef unsigned long long c64;

__device__ __forceinline__ c64 cpack(float x, float y) {
    c64 r;
    asm("mov.b64 %0, {%1, %2};" : "=l"(r) : "r"(__float_as_uint(x)), "r"(__float_as_uint(y)));
    return r;
}
__device__ __forceinline__ void cunpack(c64 a, float& x, float& y) {
    unsigned lo_, hi_;
    asm("mov.b64 {%0, %1}, %2;" : "=r"(lo_), "=r"(hi_) : "l"(a));
    x = __uint_as_float(lo_); y = __uint_as_float(hi_);
}
__device__ __forceinline__ c64 cadd(c64 a, c64 b) {
    c64 r; asm("add.rn.f32x2 %0, %1, %2;" : "=l"(r) : "l"(a), "l"(b)); return r;
}
__device__ __forceinline__ c64 cmulp(c64 a, c64 b) {
    c64 r; asm("mul.rn.f32x2 %0, %1, %2;" : "=l"(r) : "l"(a), "l"(b)); return r;
}
__device__ __forceinline__ c64 cfma(c64 a, c64 b, c64 c) {
    c64 r; asm("fma.rn.f32x2 %0, %1, %2, %3;" : "=l"(r) : "l"(a), "l"(b), "l"(c)); return r;
}
// a - b  ==  fma(b, (-1,-1), a)   (avoids relying on sub.f32x2)
__device__ __forceinline__ c64 csub(c64 a, c64 b) {
    return cfma(b, cpack(-1.0f, -1.0f), a);
}
// DIR*i*a:  DIR<0 -> (a.y, -a.x);  DIR>0 -> (-a.y, a.x)
template<int DIR>
__device__ __forceinline__ c64 cmuli(c64 a) {
    float x, y; cunpack(a, x, y);
    return (DIR < 0) ? cpack(y, -x) : cpack(-y, x);
}
// a * (c + i s), scalar twiddle (immediates when compile-time)
__device__ __forceinline__ c64 cmulw(c64 a, float c, float s) {
    float x, y; cunpack(a, x, y);
    return cpack(fmaf(x, c, -(y * s)), fmaf(y, c, x * s));
}

// constexpr tables -> guaranteed fold to immediates under full unroll
__device__ constexpr float C16f[10] = {1.f,0.92387953f,0.70710678f,0.38268343f,0.f,-0.38268343f,-0.70710678f,-0.92387953f,-1.f,-0.92387953f};
__device__ constexpr float S16f[10] = {0.f,0.38268343f,0.70710678f,0.92387953f,1.f,0.92387953f,0.70710678f,0.38268343f,0.f,-0.38268343f};
__device__ constexpr float C15f[9] = {1.f,0.91354546f,0.66913061f,0.30901699f,-0.10452846f,-0.5f,-0.80901699f,-0.97814760f,-0.97814760f};
__device__ constexpr float S15f[9] = {0.f,0.40673664f,0.74314483f,0.95105652f,0.99452190f,0.86602540f,0.58778525f,0.20791169f,-0.20791169f};

// DIR = -1 forward (e^{-i}), +1 inverse (e^{+i})
template<int DIR>
__device__ __forceinline__ void dft4p(c64 a[4]) {
    c64 u0 = cadd(a[0], a[2]);
    c64 u1 = csub(a[0], a[2]);
    c64 u2 = cadd(a[1], a[3]);
    c64 u3 = csub(a[1], a[3]);
    c64 j3 = cmuli<DIR>(u3);
    a[0] = cadd(u0, u2);
    a[2] = csub(u0, u2);
    a[1] = cadd(u1, j3);
    a[3] = csub(u1, j3);
}

template<int DIR>
__device__ __forceinline__ void fft16p(c64 a[16]) {
    c64 b[4][4];
#pragma unroll
    for (int n2 = 0; n2 < 4; n2++) {
        c64 t[4];
#pragma unroll
        for (int n1 = 0; n1 < 4; n1++) t[n1] = a[4*n1 + n2];
        dft4p<DIR>(t);
#pragma unroll
        for (int k1 = 0; k1 < 4; k1++) {
            const int j = n2 * k1;
            if (j == 0) b[n2][k1] = t[k1];
            else        b[n2][k1] = cmulw(t[k1], C16f[j], (DIR < 0) ? -S16f[j] : S16f[j]);
        }
    }
#pragma unroll
    for (int k1 = 0; k1 < 4; k1++) {
        c64 t[4];
#pragma unroll
        for (int n2 = 0; n2 < 4; n2++) t[n2] = b[n2][k1];
        dft4p<DIR>(t);
#pragma unroll
        for (int k2 = 0; k2 < 4; k2++) a[k1 + 4*k2] = t[k2];
    }
}

template<int DIR>
__device__ __forceinline__ void dft5p(c64 a[5]) {
    const c64 Kc1  = cpack( 0.309016994f,  0.309016994f);
    const c64 Kc2  = cpack(-0.809016994f, -0.809016994f);
    const c64 Ks1  = cpack( 0.951056516f,  0.951056516f);
    const c64 Ks2  = cpack( 0.587785252f,  0.587785252f);
    const c64 Kns1 = cpack(-0.951056516f, -0.951056516f);
    c64 t1 = cadd(a[1], a[4]);
    c64 t2 = cadd(a[2], a[3]);
    c64 t3 = csub(a[1], a[4]);
    c64 t4 = csub(a[2], a[3]);
    c64 m1 = cfma(t1, Kc1, cfma(t2, Kc2, a[0]));
    c64 m2 = cfma(t1, Kc2, cfma(t2, Kc1, a[0]));
    c64 p1 = cfma(t4, Ks2,  cmulp(t3, Ks1));
    c64 p2 = cfma(t4, Kns1, cmulp(t3, Ks2));
    c64 j1 = cmuli<DIR>(p1);
    c64 j2 = cmuli<DIR>(p2);
    a[0] = cadd(a[0], cadd(t1, t2));
    a[1] = cadd(m1, j1);
    a[4] = csub(m1, j1);
    a[2] = cadd(m2, j2);
    a[3] = csub(m2, j2);
}

template<int DIR>
__device__ __forceinline__ void dft3p(c64 a[3]) {
    const float s3 = 0.866025404f;
    c64 t1 = cadd(a[1], a[2]);
    c64 t2 = csub(a[1], a[2]);
    c64 m = cfma(t1, cpack(-0.5f, -0.5f), a[0]);
    float x, y; cunpack(t2, x, y);
    c64 jt = (DIR < 0) ? cpack(s3 * y, -(s3 * x)) : cpack(-(s3 * y), s3 * x);
    a[0] = cadd(a[0], t1);
    a[1] = cadd(m, jt);
    a[2] = csub(m, jt);
}

template<int DIR>
__device__ __forceinline__ void fft15p(c64 a[15]) {
    c64 c[3][5];
#pragma unroll
    for (int m2 = 0; m2 < 3; m2++) {
        c64 t[5];
#pragma unroll
        for (int m1 = 0; m1 < 5; m1++) t[m1] = a[3*m1 + m2];
        dft5p<DIR>(t);
#pragma unroll
        for (int p1 = 0; p1 < 5; p1++) {
            const int j = m2 * p1;
            if (j == 0) c[m2][p1] = t[p1];
            else        c[m2][p1] = cmulw(t[p1], C15f[j], (DIR < 0) ? -S15f[j] : S15f[j]);
        }
    }
#pragma unroll
    for (int p1 = 0; p1 < 5; p1++) {
        c64 t[3] = {c[0][p1], c[1][p1], c[2][p1]};
        dft3p<DIR>(t);
        a[p1]      = t[0];
        a[p1 + 5]  = t[1];
        a[p1 + 10] = t[2];
    }
}

// ---- stage pieces on an AOS c64 smem row v[240] (stride-241 rows) ----

template<int DIR>
__device__ __forceinline__ void stage1_tail(c64 a[16], c64* v, int t) {
#pragma unroll
    for (int k1 = 1; k1 < 16; k1++) {
        float2 w = __ldg(&g_tw[t * k1]);
        a[k1] = cmulw(a[k1], w.x, (DIR > 0) ? -w.y : w.y);
    }
#pragma unroll
    for (int k1 = 0; k1 < 16; k1++) v[15*k1 + t] = a[k1];
}

template<int DIR>
__device__ __forceinline__ void stage1_s(c64* v, int t) {
    if (t < 15) {
        c64 a[16];
#pragma unroll
        for (int n1 = 0; n1 < 16; n1++) a[n1] = v[15*n1 + t];
        fft16p<DIR>(a);
        stage1_tail<DIR>(a, v, t);
    }
    __syncwarp();
}

// stage 1, complex fp16 inputs from global (L2-resident scratch, last use)
template<int DIR>
__device__ __forceinline__ void stage1_gh(const __half2* __restrict__ gsrc,
                                          c64* v, int t) {
    if (t < 15) {
        c64 a[16];
#pragma unroll
        for (int n1 = 0; n1 < 16; n1++) {
            float2 f = __half22float2(__ldcs(&gsrc[15*n1 + t]));
            a[n1] = cpack(f.x, f.y);
        }
        fft16p<DIR>(a);
        stage1_tail<DIR>(a, v, t);
    }
    __syncwarp();
}

// stage 1, PACKED pair of real rows (a + i*b) loaded directly from global
__device__ __forceinline__ void stage1_g_pair(const float* __restrict__ ra,
                                              const float* __restrict__ rb,
                                              c64* v, int t) {
    if (t < 15) {
        c64 a[16];
#pragma unroll
        for (int n1 = 0; n1 < 16; n1++)
            a[n1] = cpack(__ldcs(&ra[15*n1 + t]), __ldcs(&rb[15*n1 + t]));
        fft16p<-1>(a);
        stage1_tail<-1>(a, v, t);
    }
    __syncwarp();
}

template<int DIR>
__device__ __forceinline__ void stage2(c64* v, int t) {
    c64 b[15];
#pragma unroll
    for (int n2 = 0; n2 < 15; n2++) b[n2] = v[15*t + n2];
    fft15p<DIR>(b);
    __syncwarp();   // all cross-lane reads done before scattered writes
    if (DIR > 0) {
        const c64 Ksc = cpack(1.0f / 240.0f, 1.0f / 240.0f);
#pragma unroll
        for (int j = 0; j < 15; j++) v[t + 16*j] = cmulp(b[j], Ksc);
    } else {
#pragma unroll
        for (int j = 0; j < 15; j++) v[t + 16*j] = b[j];
    }
    __syncwarp();
}

// stage 2 inverse + magnitude, stored DIRECTLY to global (row-contiguous dst)
__device__ __forceinline__ void stage2_mag_g(const c64* v, int t,
                                             float* __restrict__ gdst) {
    c64 b[15];
#pragma unroll
    for (int n2 = 0; n2 < 15; n2++) b[n2] = v[15*t + n2];
    fft15p<1>(b);
    const float sc = 1.0f / 240.0f;
#pragma unroll
    for (int j = 0; j < 15; j++) {
        float x, y; cunpack(b[j], x, y);
        gdst[t + 16*j] = sc * sqrtf(x * x + y * y);
    }
}

// ---------------- kernels ----------------
__global__ void init_tw_kernel() {
    int j = threadIdx.x;
    if (j < 240) {
        float s, c;
        sincosf(-6.283185307179586f * (float)j / 240.0f, &s, &c);
        g_tw[j] = make_float2(c, s);
    }
}

// K1: packed forward row FFTs of real input -> g_s1h[b][kw<128][h]
// 384 threads, 12 warps; warp w does packed FFTs p=2w (h=0) and p=2w+1 (h=1);
// packed FFT p covers real rows (h0+2p, h0+2p+1).  grid.x = 5 (48 rows/block).
__global__ __launch_bounds__(384) void k_rowfft(const float* __restrict__ x) {
    __shared__ c64 S1[24 * RSTRIDE];
    const int b = blockIdx.y;
    const int h0 = blockIdx.x * 48;
    const int tid = threadIdx.x;
    const int w = tid >> 5, lane = tid & 31;
    const int t = lane & 15, h = lane >> 4;
    const int p = 2 * w + h;                 // packed index 0..23

    const float* ra = x + ((size_t)b * 240 + h0 + 2 * p) * 240;
    c64* v = S1 + p * RSTRIDE;
    stage1_g_pair(ra, ra + 240, v, t);
    stage2<-1>(v, t);
    __syncthreads();

    // separation + transposed fp16 store: Z = FFT(a+ib) ->
    //   A[k] = (Z[k]+conj(Z[m]))/2,  B[k] = -i(Z[k]-conj(Z[m]))/2,  m=(240-k)%240
    {
        const int hh = tid % 48;
        const int kwb = tid / 48;            // 0..7
        const int pp = hh >> 1, e = hh & 1;
        const c64* Z = S1 + pp * RSTRIDE;
        __half2* dst = g_s1h + ((size_t)b * 128) * 240 + h0 + hh;
#pragma unroll
        for (int jj = 0; jj < 16; jj++) {
            int kw = kwb * 16 + jj;          // 0..127
            int m = (kw == 0) ? 0 : 240 - kw;
            float x1, y1, x2, y2;
            cunpack(Z[kw], x1, y1);
            cunpack(Z[m],  x2, y2);
            float2 vo;
            if (e == 0) vo = make_float2(0.5f * (x1 + x2), 0.5f * (y1 - y2));
            else        vo = make_float2(0.5f * (y1 + y2), 0.5f * (x2 - x1));
            dst[(size_t)kw * 240] = __floats2half2_rn(vo.x, vo.y);
        }
    }
}

// K2: fwd column FFT of 16 primary cols (warps 0-7, deduped) + Hermitian mirror
// reconstruction + combine + 32 column IFFTs (all 16 warps).  512 threads.
__global__ __launch_bounds__(512, 2) void k_colfft(const float* __restrict__ yk,
                                                   const float* __restrict__ Am) {
    extern __shared__ c64 S2[];              // 32 rows x RSTRIDE
    const int b = blockIdx.y;
    const int kw0 = blockIdx.x * 16;     // blockIdx.x in [0,8) -> primaries 0..127
    const int tid = threadIdx.x;
    const int w = tid >> 5, lane = tid & 31;
    const int t = lane & 15;
    const int h = lane >> 4;

    // ---- forward FFT of 16 primary columns: warps 0-7 own rows 2w, 2w+1;
    // warps 8-15 go straight to the barrier (no duplicated loads/FLOPs) ----
    if (w < 8) {
        const int row = 2 * w + h;
        c64* v = S2 + row * RSTRIDE;
        const __half2* gsrc = g_s1h + ((size_t)b * 128 + kw0 + row) * 240;
        stage1_gh<-1>(gsrc, v, t);           // L2 hits from K1's fresh stores
        stage2<-1>(v, t);
    }
    __syncthreads();

    const float* yr = yk + (size_t)b * (2 * NPIX);
    const float* yi = yr + NPIX;

    // ---- mirror build + combine: row 16+v <- (1-A')*conj(rev(row v)) + y' ----
    {
        const int v = tid & 15;
        const int khb = tid >> 4;            // 0..31
        const int kwm = (240 - (kw0 + v)) % 240;
        const c64* P = S2 + v * RSTRIDE;
        c64* M = S2 + (16 + v) * RSTRIDE;
#pragma unroll
        for (int j = 0; j < 8; j++) {
            int kh = khb + 32 * j;
            if (kh < 240) {
                int s = (kh == 0) ? 0 : 240 - kh;
                int idx = kh * 240 + kwm;
                float a = 1.0f - __ldg(&Am[idx]);
                float zx, zy; cunpack(P[s], zx, zy);
                M[kh] = cpack( zx * a + __ldcs(&yr[idx]),
                              -zy * a + __ldcs(&yi[idx]));
            }
        }
    }
    __syncthreads();

    // ---- primary combine in place ----
    {
        const int v = tid & 15;
        const int khb = tid >> 4;
        c64* P = S2 + v * RSTRIDE;
#pragma unroll
        for (int j = 0; j < 8; j++) {
            int kh = khb + 32 * j;
            if (kh < 240) {
                int idx = kh * 240 + kw0 + v;
                float a = 1.0f - __ldg(&Am[idx]);
                float zx, zy; cunpack(P[kh], zx, zy);
                P[kh] = cpack(zx * a + __ldcs(&yr[idx]),
                              zy * a + __ldcs(&yi[idx]));
            }
        }
    }
    __syncthreads();

    // ---- inverse FFT of all 32 rows: warp w owns rows 2w, 2w+1 ----
    {
        c64* v = S2 + (2 * w + h) * RSTRIDE;
        stage1_s<1>(v, t);
        stage2<1>(v, t);
    }
    __syncthreads();

    // ---- transposed fp16 store: primaries always; mirrors only if kwm >= 128
    // (masks the redundant overlap -> each g_s2h word written exactly once) ----
    {
        const int v = tid & 15;
        const int hb = tid >> 4;             // 0..31
        const c64* P = S2 + v * RSTRIDE;
        const c64* M = S2 + (16 + v) * RSTRIDE;
        const int kwm = (240 - (kw0 + v)) % 240;
        __half2* dstP = g_s2h + (size_t)b * NPIX + kw0 + v;
        __half2* dstM = g_s2h + (size_t)b * NPIX + kwm;
        const bool storeM = (kwm >= 128);
#pragma unroll
        for (int j = 0; j < 8; j++) {
            int hh = hb + 32 * j;
            if (hh < 240) {
                float px, py; cunpack(P[hh], px, py);
                dstP[(size_t)hh * 240] = __floats2half2_rn(px, py);
                if (storeM) {
                    float mx, my; cunpack(M[hh], mx, my);
                    dstM[(size_t)hh * 240] = __floats2half2_rn(mx, my);
                }
            }
        }
    }
}

// K3: inverse row FFTs + abs -> out[b][h][w]  (zero staging, no block sync)
__global__ __launch_bounds__(256) void k_invrow(float* __restrict__ out) {
    __shared__ c64 S3[16 * RSTRIDE];
    const int b = blockIdx.y;
    const int h0 = blockIdx.x * 16;
    const int tid = threadIdx.x;
    const int w = tid >> 5, lane = tid & 31;
    const int t = lane & 15, h = lane >> 4;

    c64* v = S3 + (2 * w + h) * RSTRIDE;

    const __half2* gsrc = g_s2h + ((size_t)b * 240 + h0 + 2 * w + h) * 240;
    stage1_gh<1>(gsrc, v, t);                // L2-resident fp16, last use

    float* ob = out + ((size_t)b * 240 + h0 + 2 * w + h) * 240;
    stage2_mag_g(v, t, ob);
}

extern "C" void kernel_launch(void* const* d_in, const int* in_sizes, int n_in,
                              void* d_out, int out_size) {
    const float* T2_Gen    = (const float*)d_in[0];  // [B,1,240,240] f32
    const float* underT2_K = (const float*)d_in[1];  // [B,2,240,240] f32
    const float* A         = (const float*)d_in[2];  // [240,240] f32
    float* out = (float*)d_out;

    int B = in_sizes[0] / NPIX;   // 256

    const int k2_smem = 32 * RSTRIDE * (int)sizeof(c64);   // 61,696 B
    cudaFuncSetAttribute(k_colfft, cudaFuncAttributeMaxDynamicSharedMemorySize, k2_smem);

    init_tw_kernel<<<1, 256>>>();
    k_rowfft<<<dim3(5, B), 384>>>(T2_Gen);
    k_colfft<<<dim3(8, B), 512, k2_smem>>>(underT2_K, A);
    k_invrow<<<dim3(15, B), 256>>>(out);
}